// round 1
// baseline (speedup 1.0000x reference)
#include <cuda_runtime.h>
#include <math.h>

#define HID 256
#define NNODES 8192
#define BSESS 512
#define NITEMS 100000

// ---------------- static scratch (no allocations allowed) ----------------
constexpr size_t NH = (size_t)NNODES * HID;           // 2,097,152
constexpr size_t OFF_T1   = 0;
constexpr size_t OFF_H    = 1 * NH;
constexpr size_t OFF_T2   = 2 * NH;
constexpr size_t OFF_Z    = 3 * NH;
constexpr size_t OFF_Q2   = 4 * NH;
constexpr size_t OFF_Q1S  = 5 * NH;                   // 512*256
constexpr size_t OFF_SG   = OFF_Q1S + (size_t)BSESS * HID;
constexpr size_t OFF_SHT  = OFF_SG  + (size_t)BSESS * HID;   // [256][512]
constexpr size_t OFF_W1T  = OFF_SHT + (size_t)HID * BSESS;
constexpr size_t OFF_W2T  = OFF_W1T + (size_t)HID * HID;
constexpr size_t OFF_WF1T = OFF_W2T + (size_t)HID * HID;
constexpr size_t OFF_WF2T = OFF_WF1T + (size_t)HID * HID;
constexpr size_t OFF_WF4T = OFF_WF2T + (size_t)HID * HID;    // [512][256]
constexpr size_t OFF_MAX  = OFF_WF4T + (size_t)2 * HID * HID;
constexpr size_t OFF_SUM  = OFF_MAX + BSESS;
constexpr size_t BUF_TOTAL = OFF_SUM + BSESS;

__device__ float g_buf[BUF_TOTAL];

// ---------------- transpose: Wt[j*R + i] = W[i*C + j] ----------------
__global__ void transpose_k(const float* __restrict__ W, float* __restrict__ Wt,
                            int R, int C)
{
    __shared__ float tile[32][33];
    int c0 = blockIdx.x * 32, r0 = blockIdx.y * 32;
    int x = threadIdx.x, y = threadIdx.y;   // (32,8)
    #pragma unroll
    for (int dy = 0; dy < 32; dy += 8) {
        int r = r0 + y + dy, c = c0 + x;
        if (r < R && c < C) tile[y + dy][x] = W[(size_t)r * C + c];
    }
    __syncthreads();
    #pragma unroll
    for (int dy = 0; dy < 32; dy += 8) {
        int c = c0 + y + dy, r = r0 + x;    // output index (c over C, r over R)
        if (c < C && r < R) Wt[(size_t)c * R + r] = tile[x][y + dy];
    }
}

// ---------------- generic 128x128x16 fp32 tiled GEMM ----------------
// C[m,n] = sum_k A[row(m),k] * B[k,n] (+bias[n]) (+relu)
// row(m) = gidx ? gidx[m] : m  (A rows gathered; rows >= M read as zero)
// transC: store C[n*ldc + m] with the micro-tile axes swapped so that the
//         m-direction maps to threadIdx's fast axis (coalesced transposed store).
#define BM 128
#define BN 128
#define BK 16

__global__ __launch_bounds__(256)
void gemm_tiled(const float* __restrict__ A, int lda,
                const int* __restrict__ gidx,
                const float* __restrict__ B, int ldb,
                const float* __restrict__ bias,
                float* __restrict__ C, int ldc,
                int M, int N, int K, int doRelu, int transC)
{
    __shared__ __align__(16) float As[BK][BM];
    __shared__ __align__(16) float Bs[BK][BN];

    int tid = threadIdx.x;
    int tx = tid & 15, ty = tid >> 4;
    int m0 = blockIdx.y * BM;
    int n0 = blockIdx.x * BN;

    // which thread axis maps to the M-side fragment
    int ai = transC ? tx : ty;   // M-side
    int bi = transC ? ty : tx;   // N-side
    int ai4 = ai * 4, bi4 = bi * 4;

    float acc[8][8];
    #pragma unroll
    for (int i = 0; i < 8; i++)
        #pragma unroll
        for (int j = 0; j < 8; j++) acc[i][j] = 0.f;

    // A tile loader: 2x float4 per thread
    int arow = tid >> 2;              // 0..63
    int acol = (tid & 3) * 4;         // 0,4,8,12
    int r0i = m0 + arow, r1i = m0 + arow + 64;
    bool v0 = r0i < M, v1 = r1i < M;
    int gr0 = r0i, gr1 = r1i;
    if (gidx) { if (v0) gr0 = gidx[r0i]; if (v1) gr1 = gidx[r1i]; }
    const float* Arow0 = A + (size_t)gr0 * lda;
    const float* Arow1 = A + (size_t)gr1 * lda;

    // B tile loader: 2x float4 per thread
    int brow = tid >> 5;              // 0..7
    int bcol = (tid & 31) * 4;        // 0..124

    for (int k0 = 0; k0 < K; k0 += BK) {
        float4 a0 = v0 ? *(const float4*)(Arow0 + k0 + acol) : make_float4(0.f,0.f,0.f,0.f);
        float4 a1 = v1 ? *(const float4*)(Arow1 + k0 + acol) : make_float4(0.f,0.f,0.f,0.f);
        float4 b0 = *(const float4*)(B + (size_t)(k0 + brow) * ldb + n0 + bcol);
        float4 b1 = *(const float4*)(B + (size_t)(k0 + brow + 8) * ldb + n0 + bcol);

        As[acol + 0][arow] = a0.x; As[acol + 1][arow] = a0.y;
        As[acol + 2][arow] = a0.z; As[acol + 3][arow] = a0.w;
        As[acol + 0][arow + 64] = a1.x; As[acol + 1][arow + 64] = a1.y;
        As[acol + 2][arow + 64] = a1.z; As[acol + 3][arow + 64] = a1.w;
        *(float4*)&Bs[brow][bcol] = b0;
        *(float4*)&Bs[brow + 8][bcol] = b1;
        __syncthreads();

        #pragma unroll
        for (int k = 0; k < BK; k++) {
            float4 aa0 = *(const float4*)&As[k][ai4];
            float4 aa1 = *(const float4*)&As[k][64 + ai4];
            float4 bb0 = *(const float4*)&Bs[k][bi4];
            float4 bb1 = *(const float4*)&Bs[k][64 + bi4];
            float af[8] = {aa0.x, aa0.y, aa0.z, aa0.w, aa1.x, aa1.y, aa1.z, aa1.w};
            float bf[8] = {bb0.x, bb0.y, bb0.z, bb0.w, bb1.x, bb1.y, bb1.z, bb1.w};
            #pragma unroll
            for (int i = 0; i < 8; i++)
                #pragma unroll
                for (int j = 0; j < 8; j++)
                    acc[i][j] += af[i] * bf[j];
        }
        __syncthreads();
    }

    if (!transC) {
        #pragma unroll
        for (int i8 = 0; i8 < 8; i8++) {
            int m = m0 + ((i8 < 4) ? (ai4 + i8) : (64 + ai4 + i8 - 4));
            if (m >= M) continue;
            #pragma unroll
            for (int jg = 0; jg < 2; jg++) {
                int n = n0 + jg * 64 + bi4;
                float4 v;
                v.x = acc[i8][jg * 4 + 0];
                v.y = acc[i8][jg * 4 + 1];
                v.z = acc[i8][jg * 4 + 2];
                v.w = acc[i8][jg * 4 + 3];
                if (bias) {
                    v.x += bias[n + 0]; v.y += bias[n + 1];
                    v.z += bias[n + 2]; v.w += bias[n + 3];
                }
                if (doRelu) {
                    v.x = fmaxf(v.x, 0.f); v.y = fmaxf(v.y, 0.f);
                    v.z = fmaxf(v.z, 0.f); v.w = fmaxf(v.w, 0.f);
                }
                *(float4*)&C[(size_t)m * ldc + n] = v;
            }
        }
    } else {
        // C[n*ldc + m], m along fast thread axis (ai = tx) -> coalesced float4
        #pragma unroll
        for (int j8 = 0; j8 < 8; j8++) {
            int n = n0 + ((j8 < 4) ? (bi4 + j8) : (64 + bi4 + j8 - 4));
            #pragma unroll
            for (int ig = 0; ig < 2; ig++) {
                int m = m0 + ig * 64 + ai4;
                if (m >= M) continue;   // M % 4 == 0, m 4-aligned -> safe float4
                float4 v;
                v.x = acc[ig * 4 + 0][j8];
                v.y = acc[ig * 4 + 1][j8];
                v.z = acc[ig * 4 + 2][j8];
                v.w = acc[ig * 4 + 3][j8];
                *(float4*)&C[(size_t)n * ldc + m] = v;
            }
        }
    }
}

// ---------------- zero scratch ----------------
__global__ void zero_k(float* p, int n)
{
    for (int i = blockIdx.x * blockDim.x + threadIdx.x; i < n; i += gridDim.x * blockDim.x)
        p[i] = 0.f;
}

// ---------------- attention gate + gated scatter-add pooling ----------------
__global__ void alpha_scatter(const float* __restrict__ q1s, const float* __restrict__ q2,
                              const float* __restrict__ z, const float* __restrict__ Wf3,
                              const int* __restrict__ idx, float* __restrict__ sg)
{
    int n = blockIdx.x;
    int c = threadIdx.x;                 // 256
    int b = idx[n];
    float q = q1s[b * HID + c] + q2[(size_t)n * HID + c];
    float sig = 1.f / (1.f + __expf(-q));
    float t = sig * Wf3[c];
    #pragma unroll
    for (int o = 16; o > 0; o >>= 1) t += __shfl_xor_sync(0xffffffffu, t, o);
    __shared__ float red[8];
    if ((c & 31) == 0) red[c >> 5] = t;
    __syncthreads();
    float alpha = red[0] + red[1] + red[2] + red[3] + red[4] + red[5] + red[6] + red[7];
    atomicAdd(&sg[b * HID + c], alpha * z[(size_t)n * HID + c]);
}

// ---------------- sh = [sl | sg] @ Wf4^T + bf4, stored transposed [HID][B] ----------------
__global__ void sh_kernel(const float* __restrict__ z, const int* __restrict__ last_item,
                          const float* __restrict__ sg, const float* __restrict__ wf4t,
                          const float* __restrict__ bf4, float* __restrict__ shT)
{
    int b = blockIdx.x;
    int c = threadIdx.x;                 // 256
    __shared__ float srow[2 * HID];
    int li = last_item[b];
    srow[c]       = z[(size_t)li * HID + c];
    srow[HID + c] = sg[b * HID + c];
    __syncthreads();
    float acc = bf4[c];
    #pragma unroll 8
    for (int k = 0; k < 2 * HID; k++)
        acc += srow[k] * wf4t[k * HID + c];
    shT[c * BSESS + b] = acc;
}

// ---------------- softmax over items, per session (row of d_out) ----------------
__global__ void softmax_reduce(const float* __restrict__ out,
                               float* __restrict__ gmax, float* __restrict__ gsum)
{
    int b = blockIdx.x;
    int t = threadIdx.x;                 // 256
    const float* row = out + (size_t)b * NITEMS;
    float m = -1e30f, s = 0.f;
    for (int i = t; i < NITEMS; i += 256) {
        float v = row[i];
        if (v > m) { s = s * __expf(m - v) + 1.f; m = v; }
        else       { s += __expf(v - m); }
    }
    __shared__ float sm[256], ss[256];
    sm[t] = m; ss[t] = s;
    __syncthreads();
    for (int o = 128; o > 0; o >>= 1) {
        if (t < o) {
            float m2 = sm[t + o], s2 = ss[t + o];
            float M2 = fmaxf(sm[t], m2);
            ss[t] = ss[t] * __expf(sm[t] - M2) + s2 * __expf(m2 - M2);
            sm[t] = M2;
        }
        __syncthreads();
    }
    if (t == 0) { gmax[b] = sm[0]; gsum[b] = ss[0]; }
}

__global__ void softmax_write(float* __restrict__ out,
                              const float* __restrict__ gmax, const float* __restrict__ gsum)
{
    int b  = blockIdx.y;
    int i4 = blockIdx.x * blockDim.x + threadIdx.x;
    if (i4 * 4 >= NITEMS) return;
    float m = gmax[b];
    float inv = 1.f / gsum[b];
    float4* p = (float4*)(out + (size_t)b * NITEMS) + i4;
    float4 v = *p;
    v.x = __expf(v.x - m) * inv;
    v.y = __expf(v.y - m) * inv;
    v.z = __expf(v.z - m) * inv;
    v.w = __expf(v.w - m) * inv;
    *p = v;
}

// ---------------- launcher ----------------
extern "C" void kernel_launch(void* const* d_in, const int* in_sizes, int n_in,
                              void* d_out, int out_size)
{
    const float* adj       = (const float*)d_in[0];
    const int*   items     = (const int*)  d_in[1];
    const int*   last_item = (const int*)  d_in[2];
    const int*   idx       = (const int*)  d_in[3];
    const float* emb       = (const float*)d_in[4];
    const float* W1  = (const float*)d_in[5];
    const float* b1  = (const float*)d_in[6];
    const float* W2  = (const float*)d_in[7];
    const float* b2  = (const float*)d_in[8];
    const float* Wf1 = (const float*)d_in[9];
    const float* bf1 = (const float*)d_in[10];
    const float* Wf2 = (const float*)d_in[11];
    const float* bf2 = (const float*)d_in[12];
    const float* Wf3 = (const float*)d_in[13];
    const float* Wf4 = (const float*)d_in[14];
    const float* bf4 = (const float*)d_in[15];
    float* out = (float*)d_out;

    float* base = nullptr;
    cudaGetSymbolAddress((void**)&base, g_buf);
    float* t1   = base + OFF_T1;
    float* h    = base + OFF_H;
    float* t2   = base + OFF_T2;
    float* z    = base + OFF_Z;
    float* q2   = base + OFF_Q2;
    float* q1s  = base + OFF_Q1S;
    float* sg   = base + OFF_SG;
    float* shT  = base + OFF_SHT;
    float* w1t  = base + OFF_W1T;
    float* w2t  = base + OFF_W2T;
    float* wf1t = base + OFF_WF1T;
    float* wf2t = base + OFF_WF2T;
    float* wf4t = base + OFF_WF4T;
    float* gmax = base + OFF_MAX;
    float* gsum = base + OFF_SUM;

    dim3 tb(32, 8);
    transpose_k<<<dim3(8, 8),  tb>>>(W1,  w1t,  HID, HID);
    transpose_k<<<dim3(8, 8),  tb>>>(W2,  w2t,  HID, HID);
    transpose_k<<<dim3(8, 8),  tb>>>(Wf1, wf1t, HID, HID);
    transpose_k<<<dim3(8, 8),  tb>>>(Wf2, wf2t, HID, HID);
    transpose_k<<<dim3(16, 8), tb>>>(Wf4, wf4t, HID, 2 * HID);

    zero_k<<<256, 256>>>(sg, BSESS * HID);

    // t1 = emb[items] @ W1^T + b1        [8192, 256]
    gemm_tiled<<<dim3(2, 64), 256>>>(emb, HID, items, w1t, HID, b1,
                                     t1, HID, NNODES, HID, HID, 0, 0);
    // h = relu(adj @ t1)                 [8192, 256]
    gemm_tiled<<<dim3(2, 64), 256>>>(adj, NNODES, nullptr, t1, HID, nullptr,
                                     h, HID, NNODES, HID, NNODES, 1, 0);
    // t2 = h @ W2^T + b2
    gemm_tiled<<<dim3(2, 64), 256>>>(h, HID, nullptr, w2t, HID, b2,
                                     t2, HID, NNODES, HID, HID, 0, 0);
    // z = adj @ t2
    gemm_tiled<<<dim3(2, 64), 256>>>(adj, NNODES, nullptr, t2, HID, nullptr,
                                     z, HID, NNODES, HID, NNODES, 0, 0);
    // q1s = z[last_item] @ Wf1^T + bf1   [512, 256]
    gemm_tiled<<<dim3(2, 4), 256>>>(z, HID, last_item, wf1t, HID, bf1,
                                    q1s, HID, BSESS, HID, HID, 0, 0);
    // q2 = z @ Wf2^T + bf2               [8192, 256]
    gemm_tiled<<<dim3(2, 64), 256>>>(z, HID, nullptr, wf2t, HID, bf2,
                                     q2, HID, NNODES, HID, HID, 0, 0);
    // alpha gate + gated scatter-add pooling into sg
    alpha_scatter<<<NNODES, 256>>>(q1s, q2, z, Wf3, idx, sg);
    // shT[k][b] = ([sl|sg] @ Wf4^T + bf4)[b][k]
    sh_kernel<<<BSESS, 256>>>(z, last_item, sg, wf4t, bf4, shT);
    // logits: out[b, i] = sum_c emb[i,c] * sh[b,c]   (store transposed into d_out)
    gemm_tiled<<<dim3(4, 782), 256>>>(emb, HID, nullptr, shT, BSESS, nullptr,
                                      out, NITEMS, NITEMS, BSESS, HID, 0, 1);
    // softmax over items per session, in place
    softmax_reduce<<<BSESS, 256>>>(out, gmax, gsum);
    softmax_write<<<dim3((NITEMS / 4 + 255) / 256, BSESS), 256>>>(out, gmax, gsum);
}

// round 2
// speedup vs baseline: 1.0024x; 1.0024x over previous
#include <cuda_runtime.h>
#include <math.h>

#define HID 256
#define NNODES 8192
#define BSESS 512
#define NITEMS 100000

// ---------------- static scratch (no allocations allowed) ----------------
constexpr size_t NH = (size_t)NNODES * HID;           // 2,097,152
constexpr size_t OFF_T1   = 0;
constexpr size_t OFF_H    = 1 * NH;
constexpr size_t OFF_T2   = 2 * NH;
constexpr size_t OFF_Z    = 3 * NH;
constexpr size_t OFF_Q2   = 4 * NH;
constexpr size_t OFF_Q1S  = 5 * NH;                   // 512*256
constexpr size_t OFF_SG   = OFF_Q1S + (size_t)BSESS * HID;
constexpr size_t OFF_SHT  = OFF_SG  + (size_t)BSESS * HID;   // [256][512]
constexpr size_t OFF_W1T  = OFF_SHT + (size_t)HID * BSESS;
constexpr size_t OFF_W2T  = OFF_W1T + (size_t)HID * HID;
constexpr size_t OFF_WF1T = OFF_W2T + (size_t)HID * HID;
constexpr size_t OFF_WF2T = OFF_WF1T + (size_t)HID * HID;
constexpr size_t OFF_WF4T = OFF_WF2T + (size_t)HID * HID;    // [512][256]
constexpr size_t OFF_MAX  = OFF_WF4T + (size_t)2 * HID * HID;
constexpr size_t OFF_SUM  = OFF_MAX + BSESS;
constexpr size_t BUF_TOTAL = OFF_SUM + BSESS;

__device__ float g_buf[BUF_TOTAL];

// ---------------- transpose: Wt[j*R + i] = W[i*C + j] ----------------
__global__ void transpose_k(const float* __restrict__ W, float* __restrict__ Wt,
                            int R, int C)
{
    __shared__ float tile[32][33];
    int c0 = blockIdx.x * 32, r0 = blockIdx.y * 32;
    int x = threadIdx.x, y = threadIdx.y;   // (32,8)
    #pragma unroll
    for (int dy = 0; dy < 32; dy += 8) {
        int r = r0 + y + dy, c = c0 + x;
        if (r < R && c < C) tile[y + dy][x] = W[(size_t)r * C + c];
    }
    __syncthreads();
    #pragma unroll
    for (int dy = 0; dy < 32; dy += 8) {
        int c = c0 + y + dy, r = r0 + x;    // output index (c over C, r over R)
        if (c < C && r < R) Wt[(size_t)c * R + r] = tile[x][y + dy];
    }
}

// ---------------- generic 128x128x16 fp32 tiled GEMM ----------------
// C[m,n] = sum_k A[row(m),k] * B[k,n] (+bias[n]) (+relu)
// row(m) = gidx ? gidx[m] : m  (A rows gathered; rows >= M read as zero)
// transC: store C[n*ldc + m] with the micro-tile axes swapped so that the
//         m-direction maps to threadIdx's fast axis (coalesced transposed store).
#define BM 128
#define BN 128
#define BK 16

__global__ __launch_bounds__(256)
void gemm_tiled(const float* __restrict__ A, int lda,
                const int* __restrict__ gidx,
                const float* __restrict__ B, int ldb,
                const float* __restrict__ bias,
                float* __restrict__ C, int ldc,
                int M, int N, int K, int doRelu, int transC)
{
    __shared__ __align__(16) float As[BK][BM];
    __shared__ __align__(16) float Bs[BK][BN];

    int tid = threadIdx.x;
    int tx = tid & 15, ty = tid >> 4;
    int m0 = blockIdx.y * BM;
    int n0 = blockIdx.x * BN;

    // which thread axis maps to the M-side fragment
    int ai = transC ? tx : ty;   // M-side
    int bi = transC ? ty : tx;   // N-side
    int ai4 = ai * 4, bi4 = bi * 4;

    float acc[8][8];
    #pragma unroll
    for (int i = 0; i < 8; i++)
        #pragma unroll
        for (int j = 0; j < 8; j++) acc[i][j] = 0.f;

    // A tile loader: 2x float4 per thread
    int arow = tid >> 2;              // 0..63
    int acol = (tid & 3) * 4;         // 0,4,8,12
    int r0i = m0 + arow, r1i = m0 + arow + 64;
    bool v0 = r0i < M, v1 = r1i < M;
    int gr0 = r0i, gr1 = r1i;
    if (gidx) { if (v0) gr0 = gidx[r0i]; if (v1) gr1 = gidx[r1i]; }
    const float* Arow0 = A + (size_t)gr0 * lda;
    const float* Arow1 = A + (size_t)gr1 * lda;

    // B tile loader: 2x float4 per thread
    int brow = tid >> 5;              // 0..7
    int bcol = (tid & 31) * 4;        // 0..124

    for (int k0 = 0; k0 < K; k0 += BK) {
        float4 a0 = v0 ? *(const float4*)(Arow0 + k0 + acol) : make_float4(0.f,0.f,0.f,0.f);
        float4 a1 = v1 ? *(const float4*)(Arow1 + k0 + acol) : make_float4(0.f,0.f,0.f,0.f);
        float4 b0 = *(const float4*)(B + (size_t)(k0 + brow) * ldb + n0 + bcol);
        float4 b1 = *(const float4*)(B + (size_t)(k0 + brow + 8) * ldb + n0 + bcol);

        As[acol + 0][arow] = a0.x; As[acol + 1][arow] = a0.y;
        As[acol + 2][arow] = a0.z; As[acol + 3][arow] = a0.w;
        As[acol + 0][arow + 64] = a1.x; As[acol + 1][arow + 64] = a1.y;
        As[acol + 2][arow + 64] = a1.z; As[acol + 3][arow + 64] = a1.w;
        *(float4*)&Bs[brow][bcol] = b0;
        *(float4*)&Bs[brow + 8][bcol] = b1;
        __syncthreads();

        #pragma unroll
        for (int k = 0; k < BK; k++) {
            float4 aa0 = *(const float4*)&As[k][ai4];
            float4 aa1 = *(const float4*)&As[k][64 + ai4];
            float4 bb0 = *(const float4*)&Bs[k][bi4];
            float4 bb1 = *(const float4*)&Bs[k][64 + bi4];
            float af[8] = {aa0.x, aa0.y, aa0.z, aa0.w, aa1.x, aa1.y, aa1.z, aa1.w};
            float bf[8] = {bb0.x, bb0.y, bb0.z, bb0.w, bb1.x, bb1.y, bb1.z, bb1.w};
            #pragma unroll
            for (int i = 0; i < 8; i++)
                #pragma unroll
                for (int j = 0; j < 8; j++)
                    acc[i][j] += af[i] * bf[j];
        }
        __syncthreads();
    }

    if (!transC) {
        #pragma unroll
        for (int i8 = 0; i8 < 8; i8++) {
            int m = m0 + ((i8 < 4) ? (ai4 + i8) : (64 + ai4 + i8 - 4));
            if (m >= M) continue;
            #pragma unroll
            for (int jg = 0; jg < 2; jg++) {
                int n = n0 + jg * 64 + bi4;
                float4 v;
                v.x = acc[i8][jg * 4 + 0];
                v.y = acc[i8][jg * 4 + 1];
                v.z = acc[i8][jg * 4 + 2];
                v.w = acc[i8][jg * 4 + 3];
                if (bias) {
                    v.x += bias[n + 0]; v.y += bias[n + 1];
                    v.z += bias[n + 2]; v.w += bias[n + 3];
                }
                if (doRelu) {
                    v.x = fmaxf(v.x, 0.f); v.y = fmaxf(v.y, 0.f);
                    v.z = fmaxf(v.z, 0.f); v.w = fmaxf(v.w, 0.f);
                }
                *(float4*)&C[(size_t)m * ldc + n] = v;
            }
        }
    } else {
        // C[n*ldc + m], m along fast thread axis (ai = tx) -> coalesced float4
        #pragma unroll
        for (int j8 = 0; j8 < 8; j8++) {
            int n = n0 + ((j8 < 4) ? (bi4 + j8) : (64 + bi4 + j8 - 4));
            #pragma unroll
            for (int ig = 0; ig < 2; ig++) {
                int m = m0 + ig * 64 + ai4;
                if (m >= M) continue;   // M % 4 == 0, m 4-aligned -> safe float4
                float4 v;
                v.x = acc[ig * 4 + 0][j8];
                v.y = acc[ig * 4 + 1][j8];
                v.z = acc[ig * 4 + 2][j8];
                v.w = acc[ig * 4 + 3][j8];
                *(float4*)&C[(size_t)n * ldc + m] = v;
            }
        }
    }
}

// ---------------- zero scratch ----------------
__global__ void zero_k(float* p, int n)
{
    for (int i = blockIdx.x * blockDim.x + threadIdx.x; i < n; i += gridDim.x * blockDim.x)
        p[i] = 0.f;
}

// ---------------- attention gate + gated scatter-add pooling ----------------
__global__ void alpha_scatter(const float* __restrict__ q1s, const float* __restrict__ q2,
                              const float* __restrict__ z, const float* __restrict__ Wf3,
                              const int* __restrict__ idx, float* __restrict__ sg)
{
    int n = blockIdx.x;
    int c = threadIdx.x;                 // 256
    int b = idx[n];
    float q = q1s[b * HID + c] + q2[(size_t)n * HID + c];
    float sig = 1.f / (1.f + __expf(-q));
    float t = sig * Wf3[c];
    #pragma unroll
    for (int o = 16; o > 0; o >>= 1) t += __shfl_xor_sync(0xffffffffu, t, o);
    __shared__ float red[8];
    if ((c & 31) == 0) red[c >> 5] = t;
    __syncthreads();
    float alpha = red[0] + red[1] + red[2] + red[3] + red[4] + red[5] + red[6] + red[7];
    atomicAdd(&sg[b * HID + c], alpha * z[(size_t)n * HID + c]);
}

// ---------------- sh = [sl | sg] @ Wf4^T + bf4, stored transposed [HID][B] ----------------
__global__ void sh_kernel(const float* __restrict__ z, const int* __restrict__ last_item,
                          const float* __restrict__ sg, const float* __restrict__ wf4t,
                          const float* __restrict__ bf4, float* __restrict__ shT)
{
    int b = blockIdx.x;
    int c = threadIdx.x;                 // 256
    __shared__ float srow[2 * HID];
    int li = last_item[b];
    srow[c]       = z[(size_t)li * HID + c];
    srow[HID + c] = sg[b * HID + c];
    __syncthreads();
    float acc = bf4[c];
    #pragma unroll 8
    for (int k = 0; k < 2 * HID; k++)
        acc += srow[k] * wf4t[k * HID + c];
    shT[c * BSESS + b] = acc;
}

// ---------------- softmax over items, per session (row of d_out) ----------------
__global__ void softmax_reduce(const float* __restrict__ out,
                               float* __restrict__ gmax, float* __restrict__ gsum)
{
    int b = blockIdx.x;
    int t = threadIdx.x;                 // 256
    const float* row = out + (size_t)b * NITEMS;
    float m = -1e30f, s = 0.f;
    for (int i = t; i < NITEMS; i += 256) {
        float v = row[i];
        if (v > m) { s = s * __expf(m - v) + 1.f; m = v; }
        else       { s += __expf(v - m); }
    }
    __shared__ float sm[256], ss[256];
    sm[t] = m; ss[t] = s;
    __syncthreads();
    for (int o = 128; o > 0; o >>= 1) {
        if (t < o) {
            float m2 = sm[t + o], s2 = ss[t + o];
            float M2 = fmaxf(sm[t], m2);
            ss[t] = ss[t] * __expf(sm[t] - M2) + s2 * __expf(m2 - M2);
            sm[t] = M2;
        }
        __syncthreads();
    }
    if (t == 0) { gmax[b] = sm[0]; gsum[b] = ss[0]; }
}

__global__ void softmax_write(float* __restrict__ out,
                              const float* __restrict__ gmax, const float* __restrict__ gsum)
{
    int b  = blockIdx.y;
    int i4 = blockIdx.x * blockDim.x + threadIdx.x;
    if (i4 * 4 >= NITEMS) return;
    float m = gmax[b];
    float inv = 1.f / gsum[b];
    float4* p = (float4*)(out + (size_t)b * NITEMS) + i4;
    float4 v = *p;
    v.x = __expf(v.x - m) * inv;
    v.y = __expf(v.y - m) * inv;
    v.z = __expf(v.z - m) * inv;
    v.w = __expf(v.w - m) * inv;
    *p = v;
}

// ---------------- launcher ----------------
extern "C" void kernel_launch(void* const* d_in, const int* in_sizes, int n_in,
                              void* d_out, int out_size)
{
    const float* adj       = (const float*)d_in[0];
    const int*   items     = (const int*)  d_in[1];
    const int*   last_item = (const int*)  d_in[2];
    const int*   idx       = (const int*)  d_in[3];
    const float* emb       = (const float*)d_in[4];
    const float* W1  = (const float*)d_in[5];
    const float* b1  = (const float*)d_in[6];
    const float* W2  = (const float*)d_in[7];
    const float* b2  = (const float*)d_in[8];
    const float* Wf1 = (const float*)d_in[9];
    const float* bf1 = (const float*)d_in[10];
    const float* Wf2 = (const float*)d_in[11];
    const float* bf2 = (const float*)d_in[12];
    const float* Wf3 = (const float*)d_in[13];
    const float* Wf4 = (const float*)d_in[14];
    const float* bf4 = (const float*)d_in[15];
    float* out = (float*)d_out;

    float* base = nullptr;
    cudaGetSymbolAddress((void**)&base, g_buf);
    float* t1   = base + OFF_T1;
    float* h    = base + OFF_H;
    float* t2   = base + OFF_T2;
    float* z    = base + OFF_Z;
    float* q2   = base + OFF_Q2;
    float* q1s  = base + OFF_Q1S;
    float* sg   = base + OFF_SG;
    float* shT  = base + OFF_SHT;
    float* w1t  = base + OFF_W1T;
    float* w2t  = base + OFF_W2T;
    float* wf1t = base + OFF_WF1T;
    float* wf2t = base + OFF_WF2T;
    float* wf4t = base + OFF_WF4T;
    float* gmax = base + OFF_MAX;
    float* gsum = base + OFF_SUM;

    dim3 tb(32, 8);
    transpose_k<<<dim3(8, 8),  tb>>>(W1,  w1t,  HID, HID);
    transpose_k<<<dim3(8, 8),  tb>>>(W2,  w2t,  HID, HID);
    transpose_k<<<dim3(8, 8),  tb>>>(Wf1, wf1t, HID, HID);
    transpose_k<<<dim3(8, 8),  tb>>>(Wf2, wf2t, HID, HID);
    transpose_k<<<dim3(16, 8), tb>>>(Wf4, wf4t, HID, 2 * HID);

    zero_k<<<256, 256>>>(sg, BSESS * HID);

    // t1 = emb[items] @ W1^T + b1        [8192, 256]
    gemm_tiled<<<dim3(2, 64), 256>>>(emb, HID, items, w1t, HID, b1,
                                     t1, HID, NNODES, HID, HID, 0, 0);
    // h = relu(adj @ t1)                 [8192, 256]
    gemm_tiled<<<dim3(2, 64), 256>>>(adj, NNODES, nullptr, t1, HID, nullptr,
                                     h, HID, NNODES, HID, NNODES, 1, 0);
    // t2 = h @ W2^T + b2
    gemm_tiled<<<dim3(2, 64), 256>>>(h, HID, nullptr, w2t, HID, b2,
                                     t2, HID, NNODES, HID, HID, 0, 0);
    // z = adj @ t2
    gemm_tiled<<<dim3(2, 64), 256>>>(adj, NNODES, nullptr, t2, HID, nullptr,
                                     z, HID, NNODES, HID, NNODES, 0, 0);
    // q1s = z[last_item] @ Wf1^T + bf1   [512, 256]
    gemm_tiled<<<dim3(2, 4), 256>>>(z, HID, last_item, wf1t, HID, bf1,
                                    q1s, HID, BSESS, HID, HID, 0, 0);
    // q2 = z @ Wf2^T + bf2               [8192, 256]
    gemm_tiled<<<dim3(2, 64), 256>>>(z, HID, nullptr, wf2t, HID, bf2,
                                     q2, HID, NNODES, HID, HID, 0, 0);
    // alpha gate + gated scatter-add pooling into sg
    alpha_scatter<<<NNODES, 256>>>(q1s, q2, z, Wf3, idx, sg);
    // shT[k][b] = ([sl|sg] @ Wf4^T + bf4)[b][k]
    sh_kernel<<<BSESS, 256>>>(z, last_item, sg, wf4t, bf4, shT);
    // logits: out[b, i] = sum_c emb[i,c] * sh[b,c]   (store transposed into d_out)
    gemm_tiled<<<dim3(4, 782), 256>>>(emb, HID, nullptr, shT, BSESS, nullptr,
                                      out, NITEMS, NITEMS, BSESS, HID, 0, 1);
    // softmax over items per session, in place
    softmax_reduce<<<BSESS, 256>>>(out, gmax, gsum);
    softmax_write<<<dim3((NITEMS / 4 + 255) / 256, BSESS), 256>>>(out, gmax, gsum);
}

// round 5
// speedup vs baseline: 2.1839x; 2.1788x over previous
#include <cuda_runtime.h>
#include <cuda_bf16.h>
#include <math.h>
#include <stdint.h>

#define HID 256
#define NNODES 8192
#define BSESS 512
#define NITEMS 100000
#define NITEMS_PAD 100096           // 782 * 128

// ---------------- static scratch (floats) ----------------
constexpr size_t F_XT   = 0;                             // [256][8192]
constexpr size_t F_H    = F_XT  + (size_t)HID * NNODES;  // [8192][256]
constexpr size_t F_Z    = F_H   + (size_t)NNODES * HID;
constexpr size_t F_Q2   = F_Z   + (size_t)NNODES * HID;
constexpr size_t F_Q1S  = F_Q2  + (size_t)NNODES * HID;
constexpr size_t F_SG   = F_Q1S + (size_t)BSESS * HID;
constexpr size_t F_SH   = F_SG  + (size_t)BSESS * HID;
constexpr size_t F_W1T  = F_SH  + (size_t)BSESS * HID;
constexpr size_t F_W2T  = F_W1T + (size_t)HID * HID;
constexpr size_t F_WF1T = F_W2T + (size_t)HID * HID;
constexpr size_t F_WF2T = F_WF1T + (size_t)HID * HID;
constexpr size_t F_WF4T = F_WF2T + (size_t)HID * HID;
constexpr size_t F_MAX  = F_WF4T + (size_t)2 * HID * HID;
constexpr size_t F_SUM  = F_MAX + BSESS;
constexpr size_t F_TOTAL = F_SUM + BSESS;
__device__ float g_f[F_TOTAL];

// bf16 hi/lo split buffers
__device__ __nv_bfloat16 g_adj_h[(size_t)NNODES * NNODES];
__device__ __nv_bfloat16 g_adj_l[(size_t)NNODES * NNODES];
__device__ __nv_bfloat16 g_emb_h[(size_t)NITEMS_PAD * HID];
__device__ __nv_bfloat16 g_emb_l[(size_t)NITEMS_PAD * HID];
__device__ __nv_bfloat16 g_x_h[(size_t)HID * NNODES];
__device__ __nv_bfloat16 g_x_l[(size_t)HID * NNODES];
__device__ __nv_bfloat16 g_sh_h[(size_t)BSESS * HID];
__device__ __nv_bfloat16 g_sh_l[(size_t)BSESS * HID];

// ---------------- PTX helpers ----------------
__device__ __forceinline__ uint32_t smem_u32(const void* p) {
    uint32_t a;
    asm("{ .reg .u64 t; cvta.to.shared.u64 t, %1; cvt.u32.u64 %0, t; }" : "=r"(a) : "l"(p));
    return a;
}
#define LDM_X4(r, a) \
    asm volatile("ldmatrix.sync.aligned.m8n8.x4.shared.b16 {%0,%1,%2,%3}, [%4];" \
        : "=r"((r)[0]), "=r"((r)[1]), "=r"((r)[2]), "=r"((r)[3]) : "r"(a))
#define MMA16816(c, a, b0, b1) \
    asm volatile("mma.sync.aligned.m16n8k16.row.col.f32.bf16.bf16.f32 " \
        "{%0,%1,%2,%3}, {%4,%5,%6,%7}, {%8,%9}, {%0,%1,%2,%3};" \
        : "+f"((c)[0]), "+f"((c)[1]), "+f"((c)[2]), "+f"((c)[3]) \
        : "r"((a)[0]), "r"((a)[1]), "r"((a)[2]), "r"((a)[3]), "r"(b0), "r"(b1))
#define CP_ASYNC16(dst, src) \
    asm volatile("cp.async.cg.shared.global [%0], [%1], 16;" :: "r"(dst), "l"(src) : "memory")
#define CP_COMMIT() asm volatile("cp.async.commit_group;" ::: "memory")
#define CP_WAIT1()  asm volatile("cp.async.wait_group 1;" ::: "memory")
#define CP_WAIT0()  asm volatile("cp.async.wait_group 0;" ::: "memory")

// ---------------- fp32 -> bf16 hi/lo split ----------------
__global__ void cvt_split(const float* __restrict__ src, __nv_bfloat16* __restrict__ hi,
                          __nv_bfloat16* __restrict__ lo, size_t nsrc, size_t ntot)
{
    size_t stride = (size_t)gridDim.x * blockDim.x;
    for (size_t t = (size_t)blockIdx.x * blockDim.x + threadIdx.x; t * 4 < ntot; t += stride) {
        size_t i = t * 4;
        float4 v = (i < nsrc) ? *(const float4*)(src + i) : make_float4(0.f, 0.f, 0.f, 0.f);
        float f[4] = {v.x, v.y, v.z, v.w};
        __nv_bfloat16 h[4], l[4];
        #pragma unroll
        for (int j = 0; j < 4; j++) {
            h[j] = __float2bfloat16_rn(f[j]);
            l[j] = __float2bfloat16_rn(f[j] - __bfloat162float(h[j]));
        }
        *(__nv_bfloat162*)(hi + i)     = __nv_bfloat162(h[0], h[1]);
        *(__nv_bfloat162*)(hi + i + 2) = __nv_bfloat162(h[2], h[3]);
        *(__nv_bfloat162*)(lo + i)     = __nv_bfloat162(l[0], l[1]);
        *(__nv_bfloat162*)(lo + i + 2) = __nv_bfloat162(l[2], l[3]);
    }
}

// ---------------- bf16-split GEMM (emulated fp32 via 3 MMAs) ----------------
// C[M][N] = A @ B^T where A = Ah+Al [M][K] row-major, B = Bh+Bl [N][K] row-major.
// Tiles: BM=128, BN=128, BK=32. 256 threads, 8 warps (2x4), warp tile 64x32.
#define SP_PITCH_B 80                  // bytes per smem row (40 bf16: 32 data + 8 pad)
#define SP_MATB (128 * SP_PITCH_B)     // 10240 B per matrix buffer
#define SP_STAGEB (4 * SP_MATB)        // 40960 B per stage (Ah, Al, Bh, Bl)
#define SP_SMEM (3 * SP_STAGEB)        // 122880 B

__global__ __launch_bounds__(256)
void gemm_bf16split(const __nv_bfloat16* __restrict__ Ah, const __nv_bfloat16* __restrict__ Al, int lda,
                    const __nv_bfloat16* __restrict__ Bh, const __nv_bfloat16* __restrict__ Bl, int ldb,
                    float* __restrict__ C, int ldc, int Nbound, int K, int doRelu)
{
    extern __shared__ __align__(128) char smem[];
    uint32_t sbase = smem_u32(smem);
    int tid = threadIdx.x, wid = tid >> 5, lane = tid & 31;
    int m0 = blockIdx.y * 128;
    int n0 = blockIdx.x * 128;
    int wm = (wid >> 2) * 64;
    int wn = (wid & 3) * 32;

    float acc[4][4][4];
    #pragma unroll
    for (int a = 0; a < 4; a++)
        #pragma unroll
        for (int b = 0; b < 4; b++)
            #pragma unroll
            for (int cc = 0; cc < 4; cc++) acc[a][b][cc] = 0.f;

    auto copy_stage = [&](int s, int k0e) {
        uint32_t dst0 = sbase + (uint32_t)s * SP_STAGEB;
        #pragma unroll
        for (int j = 0; j < 8; j++) {
            int c = j * 256 + tid;
            int mat = c >> 9, row = (c >> 2) & 127, cc = c & 3;
            int col = k0e + cc * 8;
            const __nv_bfloat16* g;
            if (mat == 0)      g = Ah + (size_t)(m0 + row) * lda + col;
            else if (mat == 1) g = Al + (size_t)(m0 + row) * lda + col;
            else if (mat == 2) g = Bh + (size_t)(n0 + row) * ldb + col;
            else               g = Bl + (size_t)(n0 + row) * ldb + col;
            uint32_t dst = dst0 + (uint32_t)mat * SP_MATB + (uint32_t)row * SP_PITCH_B + (uint32_t)cc * 16;
            CP_ASYNC16(dst, g);
        }
    };

    int kt = K / 32;
    copy_stage(0, 0);  CP_COMMIT();
    copy_stage(1, 32); CP_COMMIT();

    for (int ki = 0; ki < kt; ki++) {
        int s = ki % 3;
        CP_WAIT1();
        __syncthreads();
        int kn = ki + 2;
        if (kn < kt) copy_stage(kn % 3, kn * 32);
        CP_COMMIT();

        uint32_t As  = sbase + (uint32_t)s * SP_STAGEB;
        uint32_t Asl = As + SP_MATB;
        uint32_t Bs  = As + 2 * SP_MATB;
        uint32_t Bsl = As + 3 * SP_MATB;

        #pragma unroll
        for (int kb = 0; kb < 32; kb += 16) {
            uint32_t ah[4][4], al[4][4], bh[2][4], bl[2][4];
            uint32_t aoff = (uint32_t)(wm + (lane & 15)) * SP_PITCH_B
                          + (uint32_t)(kb + ((lane >> 4) << 3)) * 2;
            #pragma unroll
            for (int mt = 0; mt < 4; mt++) {
                LDM_X4(ah[mt], As  + aoff + mt * 16 * SP_PITCH_B);
                LDM_X4(al[mt], Asl + aoff + mt * 16 * SP_PITCH_B);
            }
            uint32_t boff = (uint32_t)(wn + (lane & 7) + ((lane >> 1) & 8)) * SP_PITCH_B
                          + (uint32_t)(kb + ((lane >> 3) & 1) * 8) * 2;
            #pragma unroll
            for (int p = 0; p < 2; p++) {
                LDM_X4(bh[p], Bs  + boff + p * 16 * SP_PITCH_B);
                LDM_X4(bl[p], Bsl + boff + p * 16 * SP_PITCH_B);
            }
            #pragma unroll
            for (int mt = 0; mt < 4; mt++)
                #pragma unroll
                for (int nt = 0; nt < 4; nt++) {
                    int p = nt >> 1, q = (nt & 1) * 2;
                    MMA16816(acc[mt][nt], ah[mt], bh[p][q], bh[p][q + 1]);
                    MMA16816(acc[mt][nt], ah[mt], bl[p][q], bl[p][q + 1]);
                    MMA16816(acc[mt][nt], al[mt], bh[p][q], bh[p][q + 1]);
                }
        }
    }
    CP_WAIT0();

    #pragma unroll
    for (int mt = 0; mt < 4; mt++)
        #pragma unroll
        for (int nt = 0; nt < 4; nt++) {
            int m = m0 + wm + mt * 16 + (lane >> 2);
            int n = n0 + wn + nt * 8 + (lane & 3) * 2;
            if (n < Nbound) {
                float2 v0 = make_float2(acc[mt][nt][0], acc[mt][nt][1]);
                float2 v1 = make_float2(acc[mt][nt][2], acc[mt][nt][3]);
                if (doRelu) {
                    v0.x = fmaxf(v0.x, 0.f); v0.y = fmaxf(v0.y, 0.f);
                    v1.x = fmaxf(v1.x, 0.f); v1.y = fmaxf(v1.y, 0.f);
                }
                *(float2*)&C[(size_t)m * ldc + n] = v0;
                *(float2*)&C[(size_t)(m + 8) * ldc + n] = v1;
            }
        }
}

// ---------------- transpose ----------------
__global__ void transpose_k(const float* __restrict__ W, float* __restrict__ Wt, int R, int C)
{
    __shared__ float tile[32][33];
    int c0 = blockIdx.x * 32, r0 = blockIdx.y * 32;
    int x = threadIdx.x, y = threadIdx.y;
    #pragma unroll
    for (int dy = 0; dy < 32; dy += 8) {
        int r = r0 + y + dy, c = c0 + x;
        if (r < R && c < C) tile[y + dy][x] = W[(size_t)r * C + c];
    }
    __syncthreads();
    #pragma unroll
    for (int dy = 0; dy < 32; dy += 8) {
        int c = c0 + y + dy, r = r0 + x;
        if (c < C && r < R) Wt[(size_t)c * R + r] = tile[x][y + dy];
    }
}

// ---------------- fp32 tiled GEMM (small GEMMs) ----------------
#define BM 128
#define BN 128
#define BK 16
__global__ __launch_bounds__(256)
void gemm_tiled(const float* __restrict__ A, int lda, const int* __restrict__ gidx,
                const float* __restrict__ B, int ldb, const float* __restrict__ bias,
                float* __restrict__ C, int ldc, int M, int N, int K, int doRelu, int transC)
{
    __shared__ __align__(16) float As[BK][BM];
    __shared__ __align__(16) float Bs[BK][BN];
    int tid = threadIdx.x;
    int tx = tid & 15, ty = tid >> 4;
    int m0 = blockIdx.y * BM, n0 = blockIdx.x * BN;
    int ai = transC ? tx : ty, bi = transC ? ty : tx;
    int ai4 = ai * 4, bi4 = bi * 4;
    float acc[8][8];
    #pragma unroll
    for (int i = 0; i < 8; i++)
        #pragma unroll
        for (int j = 0; j < 8; j++) acc[i][j] = 0.f;
    int arow = tid >> 2, acol = (tid & 3) * 4;
    int r0i = m0 + arow, r1i = m0 + arow + 64;
    bool v0 = r0i < M, v1 = r1i < M;
    int gr0 = r0i, gr1 = r1i;
    if (gidx) { if (v0) gr0 = gidx[r0i]; if (v1) gr1 = gidx[r1i]; }
    const float* Arow0 = A + (size_t)gr0 * lda;
    const float* Arow1 = A + (size_t)gr1 * lda;
    int brow = tid >> 5, bcol = (tid & 31) * 4;
    for (int k0 = 0; k0 < K; k0 += BK) {
        float4 a0 = v0 ? *(const float4*)(Arow0 + k0 + acol) : make_float4(0, 0, 0, 0);
        float4 a1 = v1 ? *(const float4*)(Arow1 + k0 + acol) : make_float4(0, 0, 0, 0);
        float4 b0 = *(const float4*)(B + (size_t)(k0 + brow) * ldb + n0 + bcol);
        float4 b1 = *(const float4*)(B + (size_t)(k0 + brow + 8) * ldb + n0 + bcol);
        As[acol + 0][arow] = a0.x; As[acol + 1][arow] = a0.y;
        As[acol + 2][arow] = a0.z; As[acol + 3][arow] = a0.w;
        As[acol + 0][arow + 64] = a1.x; As[acol + 1][arow + 64] = a1.y;
        As[acol + 2][arow + 64] = a1.z; As[acol + 3][arow + 64] = a1.w;
        *(float4*)&Bs[brow][bcol] = b0;
        *(float4*)&Bs[brow + 8][bcol] = b1;
        __syncthreads();
        #pragma unroll
        for (int k = 0; k < BK; k++) {
            float4 aa0 = *(const float4*)&As[k][ai4];
            float4 aa1 = *(const float4*)&As[k][64 + ai4];
            float4 bb0 = *(const float4*)&Bs[k][bi4];
            float4 bb1 = *(const float4*)&Bs[k][64 + bi4];
            float af[8] = {aa0.x, aa0.y, aa0.z, aa0.w, aa1.x, aa1.y, aa1.z, aa1.w};
            float bf[8] = {bb0.x, bb0.y, bb0.z, bb0.w, bb1.x, bb1.y, bb1.z, bb1.w};
            #pragma unroll
            for (int i = 0; i < 8; i++)
                #pragma unroll
                for (int j = 0; j < 8; j++) acc[i][j] += af[i] * bf[j];
        }
        __syncthreads();
    }
    if (!transC) {
        #pragma unroll
        for (int i8 = 0; i8 < 8; i8++) {
            int m = m0 + ((i8 < 4) ? (ai4 + i8) : (64 + ai4 + i8 - 4));
            if (m >= M) continue;
            #pragma unroll
            for (int jg = 0; jg < 2; jg++) {
                int n = n0 + jg * 64 + bi4;
                float4 v = make_float4(acc[i8][jg*4], acc[i8][jg*4+1], acc[i8][jg*4+2], acc[i8][jg*4+3]);
                if (bias) { v.x += bias[n]; v.y += bias[n+1]; v.z += bias[n+2]; v.w += bias[n+3]; }
                if (doRelu) { v.x = fmaxf(v.x, 0.f); v.y = fmaxf(v.y, 0.f); v.z = fmaxf(v.z, 0.f); v.w = fmaxf(v.w, 0.f); }
                *(float4*)&C[(size_t)m * ldc + n] = v;
            }
        }
    } else {
        #pragma unroll
        for (int j8 = 0; j8 < 8; j8++) {
            int n = n0 + ((j8 < 4) ? (bi4 + j8) : (64 + bi4 + j8 - 4));
            float bv = bias ? bias[n] : 0.f;
            #pragma unroll
            for (int ig = 0; ig < 2; ig++) {
                int m = m0 + ig * 64 + ai4;
                if (m >= M) continue;
                float4 v = make_float4(acc[ig*4][j8]+bv, acc[ig*4+1][j8]+bv, acc[ig*4+2][j8]+bv, acc[ig*4+3][j8]+bv);
                *(float4*)&C[(size_t)n * ldc + m] = v;
            }
        }
    }
}

__global__ void zero_k(float* p, int n)
{
    for (int i = blockIdx.x * blockDim.x + threadIdx.x; i < n; i += gridDim.x * blockDim.x)
        p[i] = 0.f;
}

// ---------------- attention / pooling / softmax ----------------
__global__ void alpha_scatter(const float* __restrict__ q1s, const float* __restrict__ q2,
                              const float* __restrict__ z, const float* __restrict__ Wf3,
                              const int* __restrict__ idx, float* __restrict__ sg)
{
    int n = blockIdx.x, c = threadIdx.x;
    int b = idx[n];
    float q = q1s[b * HID + c] + q2[(size_t)n * HID + c];
    float t = Wf3[c] / (1.f + __expf(-q));
    #pragma unroll
    for (int o = 16; o > 0; o >>= 1) t += __shfl_xor_sync(0xffffffffu, t, o);
    __shared__ float red[8];
    if ((c & 31) == 0) red[c >> 5] = t;
    __syncthreads();
    float alpha = red[0] + red[1] + red[2] + red[3] + red[4] + red[5] + red[6] + red[7];
    atomicAdd(&sg[b * HID + c], alpha * z[(size_t)n * HID + c]);
}

__global__ void sh_kernel(const float* __restrict__ z, const int* __restrict__ last_item,
                          const float* __restrict__ sg, const float* __restrict__ wf4t,
                          const float* __restrict__ bf4, float* __restrict__ sh)
{
    int b = blockIdx.x, c = threadIdx.x;
    __shared__ float srow[2 * HID];
    int li = last_item[b];
    srow[c]       = z[(size_t)li * HID + c];
    srow[HID + c] = sg[b * HID + c];
    __syncthreads();
    float acc = bf4[c];
    #pragma unroll 8
    for (int k = 0; k < 2 * HID; k++) acc += srow[k] * wf4t[k * HID + c];
    sh[b * HID + c] = acc;
}

__global__ void softmax_reduce(const float* __restrict__ out,
                               float* __restrict__ gmax, float* __restrict__ gsum)
{
    int b = blockIdx.x, t = threadIdx.x;
    const float* row = out + (size_t)b * NITEMS;
    float m = -1e30f, s = 0.f;
    for (int i = t; i < NITEMS; i += 256) {
        float v = row[i];
        if (v > m) { s = s * __expf(m - v) + 1.f; m = v; }
        else       { s += __expf(v - m); }
    }
    __shared__ float sm[256], ss[256];
    sm[t] = m; ss[t] = s;
    __syncthreads();
    for (int o = 128; o > 0; o >>= 1) {
        if (t < o) {
            float m2 = sm[t + o], s2 = ss[t + o];
            float M2 = fmaxf(sm[t], m2);
            ss[t] = ss[t] * __expf(sm[t] - M2) + s2 * __expf(m2 - M2);
            sm[t] = M2;
        }
        __syncthreads();
    }
    if (t == 0) { gmax[b] = sm[0]; gsum[b] = ss[0]; }
}

__global__ void softmax_write(float* __restrict__ out,
                              const float* __restrict__ gmax, const float* __restrict__ gsum)
{
    int b = blockIdx.y;
    int i4 = blockIdx.x * blockDim.x + threadIdx.x;
    if (i4 * 4 >= NITEMS) return;
    float m = gmax[b], inv = 1.f / gsum[b];
    float4* p = (float4*)(out + (size_t)b * NITEMS) + i4;
    float4 v = *p;
    v.x = __expf(v.x - m) * inv; v.y = __expf(v.y - m) * inv;
    v.z = __expf(v.z - m) * inv; v.w = __expf(v.w - m) * inv;
    *p = v;
}

// ---------------- launcher ----------------
extern "C" void kernel_launch(void* const* d_in, const int* in_sizes, int n_in,
                              void* d_out, int out_size)
{
    const float* adj       = (const float*)d_in[0];
    const int*   items     = (const int*)  d_in[1];
    const int*   last_item = (const int*)  d_in[2];
    const int*   idx       = (const int*)  d_in[3];
    const float* emb       = (const float*)d_in[4];
    const float* W1  = (const float*)d_in[5];
    const float* b1  = (const float*)d_in[6];
    const float* W2  = (const float*)d_in[7];
    const float* b2  = (const float*)d_in[8];
    const float* Wf1 = (const float*)d_in[9];
    const float* bf1 = (const float*)d_in[10];
    const float* Wf2 = (const float*)d_in[11];
    const float* bf2 = (const float*)d_in[12];
    const float* Wf3 = (const float*)d_in[13];
    const float* Wf4 = (const float*)d_in[14];
    const float* bf4 = (const float*)d_in[15];
    float* out = (float*)d_out;

    float* fb = nullptr;
    cudaGetSymbolAddress((void**)&fb, g_f);
    float* xT   = fb + F_XT;
    float* h    = fb + F_H;
    float* z    = fb + F_Z;
    float* q2   = fb + F_Q2;
    float* q1s  = fb + F_Q1S;
    float* sg   = fb + F_SG;
    float* sh   = fb + F_SH;
    float* w1t  = fb + F_W1T;
    float* w2t  = fb + F_W2T;
    float* wf1t = fb + F_WF1T;
    float* wf2t = fb + F_WF2T;
    float* wf4t = fb + F_WF4T;
    float* gmax = fb + F_MAX;
    float* gsum = fb + F_SUM;

    __nv_bfloat16 *adjh, *adjl, *embh, *embl, *xh, *xl, *shh, *shl;
    cudaGetSymbolAddress((void**)&adjh, g_adj_h);
    cudaGetSymbolAddress((void**)&adjl, g_adj_l);
    cudaGetSymbolAddress((void**)&embh, g_emb_h);
    cudaGetSymbolAddress((void**)&embl, g_emb_l);
    cudaGetSymbolAddress((void**)&xh,   g_x_h);
    cudaGetSymbolAddress((void**)&xl,   g_x_l);
    cudaGetSymbolAddress((void**)&shh,  g_sh_h);
    cudaGetSymbolAddress((void**)&shl,  g_sh_l);

    static bool inited = false;
    if (!inited) {
        cudaFuncSetAttribute(gemm_bf16split, cudaFuncAttributeMaxDynamicSharedMemorySize, SP_SMEM);
        inited = true;
    }

    dim3 tb(32, 8);
    transpose_k<<<dim3(8, 8),  tb>>>(W1,  w1t,  HID, HID);
    transpose_k<<<dim3(8, 8),  tb>>>(W2,  w2t,  HID, HID);
    transpose_k<<<dim3(8, 8),  tb>>>(Wf1, wf1t, HID, HID);
    transpose_k<<<dim3(8, 8),  tb>>>(Wf2, wf2t, HID, HID);
    transpose_k<<<dim3(16, 8), tb>>>(Wf4, wf4t, HID, 2 * HID);
    zero_k<<<256, 256>>>(sg, BSESS * HID);

    // one-time-per-launch splits
    cvt_split<<<2048, 256>>>(adj, adjh, adjl, (size_t)NNODES * NNODES, (size_t)NNODES * NNODES);
    cvt_split<<<1024, 256>>>(emb, embh, embl, (size_t)NITEMS * HID, (size_t)NITEMS_PAD * HID);

    // t1^T = (emb[items] @ W1^T + b1)^T   [256][8192]
    gemm_tiled<<<dim3(2, 64), 256>>>(emb, HID, items, w1t, HID, b1,
                                     xT, NNODES, NNODES, HID, HID, 0, 1);
    cvt_split<<<512, 256>>>(xT, xh, xl, (size_t)HID * NNODES, (size_t)HID * NNODES);
    // h = relu(adj @ t1)
    gemm_bf16split<<<dim3(2, 64), 256, SP_SMEM>>>(adjh, adjl, NNODES, xh, xl, NNODES,
                                                  h, HID, HID, NNODES, 1);
    // t2^T = (h @ W2^T + b2)^T
    gemm_tiled<<<dim3(2, 64), 256>>>(h, HID, nullptr, w2t, HID, b2,
                                     xT, NNODES, NNODES, HID, HID, 0, 1);
    cvt_split<<<512, 256>>>(xT, xh, xl, (size_t)HID * NNODES, (size_t)HID * NNODES);
    // z = adj @ t2
    gemm_bf16split<<<dim3(2, 64), 256, SP_SMEM>>>(adjh, adjl, NNODES, xh, xl, NNODES,
                                                  z, HID, HID, NNODES, 0);
    // q1s / q2 (fp32)
    gemm_tiled<<<dim3(2, 4), 256>>>(z, HID, last_item, wf1t, HID, bf1,
                                    q1s, HID, BSESS, HID, HID, 0, 0);
    gemm_tiled<<<dim3(2, 64), 256>>>(z, HID, nullptr, wf2t, HID, bf2,
                                     q2, HID, NNODES, HID, HID, 0, 0);
    alpha_scatter<<<NNODES, 256>>>(q1s, q2, z, Wf3, idx, sg);
    sh_kernel<<<BSESS, 256>>>(z, last_item, sg, wf4t, bf4, sh);
    // logits: out[b][i] = sh[b,:] . emb[i,:]
    cvt_split<<<64, 256>>>(sh, shh, shl, (size_t)BSESS * HID, (size_t)BSESS * HID);
    gemm_bf16split<<<dim3(NITEMS_PAD / 128, BSESS / 128), 256, SP_SMEM>>>(
        shh, shl, HID, embh, embl, HID, out, NITEMS, NITEMS, HID, 0);
    // softmax in place
    softmax_reduce<<<BSESS, 256>>>(out, gmax, gsum);
    softmax_write<<<dim3((NITEMS / 4 + 255) / 256, BSESS), 256>>>(out, gmax, gsum);
}